// round 1
// baseline (speedup 1.0000x reference)
#include <cuda_runtime.h>
#include <cstdint>

#define NN 50000
#define NE 800000
#define NR 8
#define FD 128

// Scratch for per-relation transformed features: ht[n][r][o], 204.8 MB.
__device__ float g_ht[(size_t)NN * NR * FD];

// ---------------------------------------------------------------------------
// Kernel 1: ht[n, r, :] = h[n, :] @ W[r]   (fp32, register-tiled)
// Block: 64 nodes x 128 outs x one relation. 256 threads, 4x8 per thread.
// ---------------------------------------------------------------------------
__global__ __launch_bounds__(256) void rgcn_gemm(const float* __restrict__ h,
                                                 const float* __restrict__ w) {
    const int r  = blockIdx.y;
    const int m0 = blockIdx.x * 64;

    // h tile transposed: hs_t[k][node], padded row to 68 floats (272 B, 16B-aligned)
    __shared__ float hs_t[32][68];
    // W tile: ws[k][o], padded row to 132 floats (528 B, 16B-aligned)
    __shared__ float ws[32][132];

    const int tid = threadIdx.x;
    const int tx  = tid & 15;   // node group: nodes tx*4 .. tx*4+3
    const int ty  = tid >> 4;   // out group : outs  ty*8 .. ty*8+7

    float acc[4][8];
#pragma unroll
    for (int i = 0; i < 4; i++)
#pragma unroll
        for (int j = 0; j < 8; j++) acc[i][j] = 0.0f;

    const float* wr = w + (size_t)r * FD * FD;

    for (int k0 = 0; k0 < FD; k0 += 32) {
        // Load h tile (64 nodes x 32 k) coalesced, store transposed.
        {
            int row = tid >> 2;           // 0..63 (node within tile)
            int c0  = (tid & 3) * 8;      // k offset: 0,8,16,24
            int n   = m0 + row;
            float v[8];
            if (n < NN) {
                const float4* src = (const float4*)(h + (size_t)n * FD + k0 + c0);
                float4 a = src[0], b = src[1];
                v[0]=a.x; v[1]=a.y; v[2]=a.z; v[3]=a.w;
                v[4]=b.x; v[5]=b.y; v[6]=b.z; v[7]=b.w;
            } else {
#pragma unroll
                for (int q = 0; q < 8; q++) v[q] = 0.0f;
            }
#pragma unroll
            for (int q = 0; q < 8; q++) hs_t[c0 + q][row] = v[q];
        }
        // Load W tile (32 k x 128 o) coalesced.
        {
            int row = tid >> 3;           // 0..31 (k within tile)
            int c0  = (tid & 7) * 16;     // o offset
            const float4* src = (const float4*)(wr + (size_t)(k0 + row) * FD + c0);
#pragma unroll
            for (int q = 0; q < 4; q++) {
                float4 vv = src[q];
                ws[row][c0 + q*4 + 0] = vv.x;
                ws[row][c0 + q*4 + 1] = vv.y;
                ws[row][c0 + q*4 + 2] = vv.z;
                ws[row][c0 + q*4 + 3] = vv.w;
            }
        }
        __syncthreads();

#pragma unroll
        for (int k = 0; k < 32; k++) {
            float4 a4 = *(const float4*)&hs_t[k][tx * 4];     // conflict-free LDS.128
            float4 b0 = *(const float4*)&ws[k][ty * 8];       // warp-broadcast
            float4 b1 = *(const float4*)&ws[k][ty * 8 + 4];
            float a[4] = {a4.x, a4.y, a4.z, a4.w};
            float b[8] = {b0.x, b0.y, b0.z, b0.w, b1.x, b1.y, b1.z, b1.w};
#pragma unroll
            for (int i = 0; i < 4; i++)
#pragma unroll
                for (int j = 0; j < 8; j++)
                    acc[i][j] = fmaf(a[i], b[j], acc[i][j]);
        }
        __syncthreads();
    }

    // Store: ht[(n*NR + r)*FD + o]
#pragma unroll
    for (int i = 0; i < 4; i++) {
        int n = m0 + tx * 4 + i;
        if (n < NN) {
            float* dstp = g_ht + ((size_t)n * NR + r) * FD + ty * 8;
            float4 o0 = {acc[i][0], acc[i][1], acc[i][2], acc[i][3]};
            float4 o1 = {acc[i][4], acc[i][5], acc[i][6], acc[i][7]};
            ((float4*)dstp)[0] = o0;
            ((float4*)dstp)[1] = o1;
        }
    }
}

// ---------------------------------------------------------------------------
// Kernel 2: per-edge gather + scaled vector reduction into out[dst].
// One warp per edge; lane l handles floats [4l, 4l+4).
// ---------------------------------------------------------------------------
__global__ __launch_bounds__(256) void rgcn_edges(const float* __restrict__ enorm,
                                                  const int* __restrict__ etype,
                                                  const int* __restrict__ esrc,
                                                  const int* __restrict__ edst,
                                                  float* __restrict__ out) {
    const int e = blockIdx.x * 8 + (threadIdx.x >> 5);
    if (e >= NE) return;
    const int lane = threadIdx.x & 31;

    const int   s  = __ldg(esrc + e);
    const int   d  = __ldg(edst + e);
    const int   t  = __ldg(etype + e);
    const float nv = __ldg(enorm + e);

    const float4* row = (const float4*)(g_ht + ((size_t)s * NR + t) * FD);
    float4 v = row[lane];

    float* o = out + (size_t)d * FD + lane * 4;
    asm volatile("red.global.add.v4.f32 [%0], {%1, %2, %3, %4};"
                 :: "l"(o), "f"(v.x * nv), "f"(v.y * nv), "f"(v.z * nv), "f"(v.w * nv)
                 : "memory");
}

// ---------------------------------------------------------------------------
// Kernel 3: out = relu(out + bias)
// ---------------------------------------------------------------------------
__global__ __launch_bounds__(256) void rgcn_bias_relu(float* __restrict__ out,
                                                      const float* __restrict__ bias) {
    const int i = blockIdx.x * 256 + threadIdx.x;   // float4 index
    const int total = NN * FD / 4;
    if (i >= total) return;
    const int o = (i * 4) & (FD - 1);
    float4 v = ((float4*)out)[i];
    v.x = fmaxf(v.x + __ldg(bias + o + 0), 0.0f);
    v.y = fmaxf(v.y + __ldg(bias + o + 1), 0.0f);
    v.z = fmaxf(v.z + __ldg(bias + o + 2), 0.0f);
    v.w = fmaxf(v.w + __ldg(bias + o + 3), 0.0f);
    ((float4*)out)[i] = v;
}

extern "C" void kernel_launch(void* const* d_in, const int* in_sizes, int n_in,
                              void* d_out, int out_size) {
    const float* h     = (const float*)d_in[0];
    const float* enorm = (const float*)d_in[1];
    const int*   etype = (const int*)d_in[2];
    const int*   esrc  = (const int*)d_in[3];
    const int*   edst  = (const int*)d_in[4];
    const float* w     = (const float*)d_in[5];
    const float* bias  = (const float*)d_in[6];
    float* out = (float*)d_out;

    cudaMemsetAsync(out, 0, (size_t)NN * FD * sizeof(float), 0);

    dim3 gg((NN + 63) / 64, NR);
    rgcn_gemm<<<gg, 256>>>(h, w);

    rgcn_edges<<<(NE + 7) / 8, 256>>>(enorm, etype, esrc, edst, out);

    rgcn_bias_relu<<<(NN * FD / 4 + 255) / 256, 256>>>(out, bias);
}

// round 3
// speedup vs baseline: 1.2060x; 1.2060x over previous
#include <cuda_runtime.h>
#include <cuda_bf16.h>
#include <cstdint>

#define NN 50000
#define NE 800000
#define NR 8
#define FD 128

#define M_TILES ((NN + 127) / 128)        // 391
#define SMEM_BYTES (1024 + 4 * 32768)     // align slack + 4 tiles = 132096

// Scratch: ht[n][r][o] fp32, 204.8 MB.
__device__ float g_ht[(size_t)NN * NR * FD];
// W transposed + bf16-split: [r][o][i]
__device__ __nv_bfloat16 g_wb_hi[NR * FD * FD];
__device__ __nv_bfloat16 g_wb_lo[NR * FD * FD];

// ---------------------------------------------------------------------------
__device__ __forceinline__ uint32_t smem_u32(const void* p) {
    uint32_t a;
    asm("{ .reg .u64 t; cvta.to.shared.u64 t, %1; cvt.u32.u64 %0, t; }" : "=r"(a) : "l"(p));
    return a;
}

// Blocked SW128 K-major layout for a [128 rows x 128 bf16] tile.
// atom = 8 rows x 64 bf16 (1024 B); atom_offset = atom_row + atom_col*16.
__device__ __forceinline__ uint32_t tile_off(int row, int k) {
    uint32_t b = ((uint32_t)(row >> 3) + (uint32_t)(k >> 6) * 16u) * 1024u
               + (uint32_t)(row & 7) * 128u + (uint32_t)(k & 63) * 2u;
    return b ^ ((b >> 3) & 0x70u);
}

__device__ __forceinline__ void ldm_x4(uint32_t* r, uint32_t addr) {
    asm volatile("ldmatrix.sync.aligned.m8n8.x4.shared.b16 {%0,%1,%2,%3}, [%4];"
                 : "=r"(r[0]), "=r"(r[1]), "=r"(r[2]), "=r"(r[3]) : "r"(addr));
}

__device__ __forceinline__ void mma_16816(float* c, const uint32_t* a,
                                          uint32_t b0, uint32_t b1) {
    asm volatile(
        "mma.sync.aligned.m16n8k16.row.col.f32.bf16.bf16.f32 "
        "{%0,%1,%2,%3}, {%4,%5,%6,%7}, {%8,%9}, {%0,%1,%2,%3};"
        : "+f"(c[0]), "+f"(c[1]), "+f"(c[2]), "+f"(c[3])
        : "r"(a[0]), "r"(a[1]), "r"(a[2]), "r"(a[3]), "r"(b0), "r"(b1));
}

// ---------------------------------------------------------------------------
// Kernel 0: split W into bf16 hi/lo, transposed to [r][o][i].
// ---------------------------------------------------------------------------
__global__ __launch_bounds__(256) void rgcn_wprep(const float* __restrict__ w) {
    int idx = blockIdx.x * 256 + threadIdx.x;
    if (idx >= NR * FD * FD) return;
    int r = idx >> 14, rem = idx & 16383;
    int o = rem >> 7, i = rem & 127;
    float x = w[((size_t)r * FD + i) * FD + o];
    __nv_bfloat16 hi = __float2bfloat16(x);
    __nv_bfloat16 lo = __float2bfloat16(x - __bfloat162float(hi));
    g_wb_hi[idx] = hi;
    g_wb_lo[idx] = lo;
}

// ---------------------------------------------------------------------------
// Kernel 1: ht[m0+row][r][:] = h_tile @ W_r  (split bf16, mma.sync tensor cores)
// 256 threads; 4(M)x2(N) warps; warp tile 32x64; grid (NR, M_TILES).
// ---------------------------------------------------------------------------
__global__ __launch_bounds__(256, 1) void rgcn_mma_gemm(const float* __restrict__ h) {
    extern __shared__ char smem[];
    const uint32_t raw  = smem_u32(smem);
    const uint32_t base = (raw + 1023u) & ~1023u;
    char* const smem_al = smem + (base - raw);

    const uint32_t A_HI = base;
    const uint32_t A_LO = A_HI + 32768;
    const uint32_t B_HI = A_LO + 32768;
    const uint32_t B_LO = B_HI + 32768;
    char* a_hi_p = smem_al;
    char* a_lo_p = a_hi_p + 32768;
    char* b_hi_p = a_lo_p + 32768;
    char* b_lo_p = b_hi_p + 32768;

    const int tid  = threadIdx.x;
    const int wid  = tid >> 5;
    const int lane = tid & 31;
    const int r    = blockIdx.x;
    const int m0   = blockIdx.y * 128;

    // --- Load + split A tile: 128 nodes x 128 feats ---
    for (int idx = tid; idx < 8192; idx += 256) {   // float2 granules
        int row = idx >> 6;
        int k   = (idx & 63) * 2;
        int n   = m0 + row;
        float2 v = (n < NN) ? *(const float2*)(h + (size_t)n * FD + k)
                            : make_float2(0.f, 0.f);
        __nv_bfloat16 h0 = __float2bfloat16(v.x), h1 = __float2bfloat16(v.y);
        __nv_bfloat16 l0 = __float2bfloat16(v.x - __bfloat162float(h0));
        __nv_bfloat16 l1 = __float2bfloat16(v.y - __bfloat162float(h1));
        uint32_t off = tile_off(row, k);
        *(__nv_bfloat162*)(a_hi_p + off) = __nv_bfloat162(h0, h1);
        *(__nv_bfloat162*)(a_lo_p + off) = __nv_bfloat162(l0, l1);
    }
    // --- Load B tiles (bf16, [o][i]) ---
    const __nv_bfloat16* wbh = g_wb_hi + (size_t)r * FD * FD;
    const __nv_bfloat16* wbl = g_wb_lo + (size_t)r * FD * FD;
    for (int idx = tid; idx < 4096; idx += 256) {   // 4-bf16 granules
        int row = idx >> 5;
        int k   = (idx & 31) * 4;
        uint32_t off = tile_off(row, k);
        *(uint2*)(b_hi_p + off) = *(const uint2*)(wbh + row * FD + k);
        *(uint2*)(b_lo_p + off) = *(const uint2*)(wbl + row * FD + k);
    }
    __syncthreads();

    const int mwarp = wid & 3;     // 0..3 -> rows mwarp*32
    const int nwarp = wid >> 2;    // 0..1 -> cols nwarp*64

    // ldmatrix lane geometry
    const int row_a = (lane & 7) + ((lane >> 3) & 1) * 8;   // + mi*16 + mwarp*32
    const int ka    = ((lane >> 4) & 1) * 8;
    const int row_b = (lane & 7) + ((lane >> 4) & 1) * 8;   // + q*16 + nwarp*64
    const int kb    = ((lane >> 3) & 1) * 8;

    float acc[2][8][4];
#pragma unroll
    for (int mi = 0; mi < 2; mi++)
#pragma unroll
        for (int nj = 0; nj < 8; nj++)
#pragma unroll
            for (int q = 0; q < 4; q++) acc[mi][nj][q] = 0.0f;

    const uint32_t At[3] = {A_HI, A_HI, A_LO};
    const uint32_t Bt[3] = {B_HI, B_LO, B_HI};

    for (int p = 0; p < 3; p++) {
        const uint32_t Ab = At[p];
        const uint32_t Bb = Bt[p];
#pragma unroll
        for (int k0 = 0; k0 < 128; k0 += 16) {
            uint32_t af[2][4];
#pragma unroll
            for (int mi = 0; mi < 2; mi++)
                ldm_x4(af[mi], Ab + tile_off(mwarp * 32 + mi * 16 + row_a, k0 + ka));
            uint32_t bf[4][4];
#pragma unroll
            for (int q = 0; q < 4; q++)
                ldm_x4(bf[q], Bb + tile_off(nwarp * 64 + q * 16 + row_b, k0 + kb));
#pragma unroll
            for (int mi = 0; mi < 2; mi++)
#pragma unroll
                for (int nj = 0; nj < 8; nj++)
                    mma_16816(acc[mi][nj], af[mi],
                              bf[nj >> 1][(nj & 1) * 2], bf[nj >> 1][(nj & 1) * 2 + 1]);
        }
    }

    // --- Epilogue: direct stores (float2 per fragment half) ---
    const int crow = lane >> 2;
    const int ccol = (lane & 3) * 2;
#pragma unroll
    for (int mi = 0; mi < 2; mi++) {
        int row0 = mwarp * 32 + mi * 16 + crow;
        int n0 = m0 + row0;
        int n1 = n0 + 8;
        float* d0 = g_ht + ((size_t)n0 * NR + r) * FD + nwarp * 64 + ccol;
        float* d1 = g_ht + ((size_t)n1 * NR + r) * FD + nwarp * 64 + ccol;
#pragma unroll
        for (int nj = 0; nj < 8; nj++) {
            if (n0 < NN) *(float2*)(d0 + nj * 8) = make_float2(acc[mi][nj][0], acc[mi][nj][1]);
            if (n1 < NN) *(float2*)(d1 + nj * 8) = make_float2(acc[mi][nj][2], acc[mi][nj][3]);
        }
    }
}

// ---------------------------------------------------------------------------
// Kernel 2: per-edge gather + scaled vector reduction into out[dst].
// ---------------------------------------------------------------------------
__global__ __launch_bounds__(256) void rgcn_edges(const float* __restrict__ enorm,
                                                  const int* __restrict__ etype,
                                                  const int* __restrict__ esrc,
                                                  const int* __restrict__ edst,
                                                  float* __restrict__ out) {
    const int e = blockIdx.x * 8 + (threadIdx.x >> 5);
    if (e >= NE) return;
    const int lane = threadIdx.x & 31;

    const int   s  = __ldg(esrc + e);
    const int   d  = __ldg(edst + e);
    const int   t  = __ldg(etype + e);
    const float nv = __ldg(enorm + e);

    const float4* row = (const float4*)(g_ht + ((size_t)s * NR + t) * FD);
    float4 v = row[lane];

    float* o = out + (size_t)d * FD + lane * 4;
    asm volatile("red.global.add.v4.f32 [%0], {%1, %2, %3, %4};"
                 :: "l"(o), "f"(v.x * nv), "f"(v.y * nv), "f"(v.z * nv), "f"(v.w * nv)
                 : "memory");
}

// ---------------------------------------------------------------------------
// Kernel 3: out = relu(out + bias)
// ---------------------------------------------------------------------------
__global__ __launch_bounds__(256) void rgcn_bias_relu(float* __restrict__ out,
                                                      const float* __restrict__ bias) {
    const int i = blockIdx.x * 256 + threadIdx.x;
    const int total = NN * FD / 4;
    if (i >= total) return;
    const int o = (i * 4) & (FD - 1);
    float4 v = ((float4*)out)[i];
    v.x = fmaxf(v.x + __ldg(bias + o + 0), 0.0f);
    v.y = fmaxf(v.y + __ldg(bias + o + 1), 0.0f);
    v.z = fmaxf(v.z + __ldg(bias + o + 2), 0.0f);
    v.w = fmaxf(v.w + __ldg(bias + o + 3), 0.0f);
    ((float4*)out)[i] = v;
}

extern "C" void kernel_launch(void* const* d_in, const int* in_sizes, int n_in,
                              void* d_out, int out_size) {
    const float* h     = (const float*)d_in[0];
    const float* enorm = (const float*)d_in[1];
    const int*   etype = (const int*)d_in[2];
    const int*   esrc  = (const int*)d_in[3];
    const int*   edst  = (const int*)d_in[4];
    const float* w     = (const float*)d_in[5];
    const float* bias  = (const float*)d_in[6];
    float* out = (float*)d_out;

    cudaFuncSetAttribute(rgcn_mma_gemm, cudaFuncAttributeMaxDynamicSharedMemorySize,
                         SMEM_BYTES);

    cudaMemsetAsync(out, 0, (size_t)NN * FD * sizeof(float), 0);

    rgcn_wprep<<<(NR * FD * FD + 255) / 256, 256>>>(w);

    dim3 gg(NR, M_TILES);
    rgcn_mma_gemm<<<gg, 256, SMEM_BYTES>>>(h);

    rgcn_edges<<<(NE + 7) / 8, 256>>>(enorm, etype, esrc, edst, out);

    rgcn_bias_relu<<<(NN * FD / 4 + 255) / 256, 256>>>(out, bias);
}

// round 5
// speedup vs baseline: 1.3493x; 1.1189x over previous
#include <cuda_runtime.h>
#include <cuda_bf16.h>
#include <cstdint>

#define NN 50000
#define NE 800000
#define NR 8
#define FD 128

#define M_TILES ((NN + 127) / 128)        // 391
#define SMEM_BYTES (1024 + 2 * 32768)     // align slack + A + B = 66560

// Scratch: ht[n][r][o] fp32, 204.8 MB.
__device__ float g_ht[(size_t)NN * NR * FD];
// W transposed + bf16-split: [r][o][i]
__device__ __nv_bfloat16 g_wb_hi[NR * FD * FD];
__device__ __nv_bfloat16 g_wb_lo[NR * FD * FD];
// h bf16-split: [n][i]
__device__ __nv_bfloat16 g_hb_hi[(size_t)NN * FD];
__device__ __nv_bfloat16 g_hb_lo[(size_t)NN * FD];

// ---------------------------------------------------------------------------
__device__ __forceinline__ uint32_t smem_u32(const void* p) {
    uint32_t a;
    asm("{ .reg .u64 t; cvta.to.shared.u64 t, %1; cvt.u32.u64 %0, t; }" : "=r"(a) : "l"(p));
    return a;
}

// Blocked SW128 K-major layout for a [128 rows x 128 bf16] tile.
__device__ __forceinline__ uint32_t tile_off(int row, int k) {
    uint32_t b = ((uint32_t)(row >> 3) + (uint32_t)(k >> 6) * 16u) * 1024u
               + (uint32_t)(row & 7) * 128u + (uint32_t)(k & 63) * 2u;
    return b ^ ((b >> 3) & 0x70u);
}

__device__ __forceinline__ void ldm_x4(uint32_t* r, uint32_t addr) {
    asm volatile("ldmatrix.sync.aligned.m8n8.x4.shared.b16 {%0,%1,%2,%3}, [%4];"
                 : "=r"(r[0]), "=r"(r[1]), "=r"(r[2]), "=r"(r[3]) : "r"(addr));
}

__device__ __forceinline__ void mma_16816(float* c, const uint32_t* a,
                                          uint32_t b0, uint32_t b1) {
    asm volatile(
        "mma.sync.aligned.m16n8k16.row.col.f32.bf16.bf16.f32 "
        "{%0,%1,%2,%3}, {%4,%5,%6,%7}, {%8,%9}, {%0,%1,%2,%3};"
        : "+f"(c[0]), "+f"(c[1]), "+f"(c[2]), "+f"(c[3])
        : "r"(a[0]), "r"(a[1]), "r"(a[2]), "r"(a[3]), "r"(b0), "r"(b1));
}

__device__ __forceinline__ void cpasync16(uint32_t dst, const void* src, int sz) {
    asm volatile("cp.async.cg.shared.global [%0], [%1], 16, %2;"
                 :: "r"(dst), "l"(src), "r"(sz) : "memory");
}
#define CP_COMMIT() asm volatile("cp.async.commit_group;" ::: "memory")
#define CP_WAIT0()  asm volatile("cp.async.wait_group 0;" ::: "memory")

// ---------------------------------------------------------------------------
// Kernel 0a: split W into bf16 hi/lo, transposed to [r][o][i].
// ---------------------------------------------------------------------------
__global__ __launch_bounds__(256) void rgcn_wprep(const float* __restrict__ w) {
    int idx = blockIdx.x * 256 + threadIdx.x;
    if (idx >= NR * FD * FD) return;
    int r = idx >> 14, rem = idx & 16383;
    int o = rem >> 7, i = rem & 127;
    float x = w[((size_t)r * FD + i) * FD + o];
    __nv_bfloat16 hi = __float2bfloat16(x);
    __nv_bfloat16 lo = __float2bfloat16(x - __bfloat162float(hi));
    g_wb_hi[idx] = hi;
    g_wb_lo[idx] = lo;
}

// ---------------------------------------------------------------------------
// Kernel 0b: split h into bf16 hi/lo.
// ---------------------------------------------------------------------------
__global__ __launch_bounds__(256) void rgcn_hprep(const float* __restrict__ h) {
    int idx = blockIdx.x * 256 + threadIdx.x;        // float2 granule
    const int total = NN * FD / 2;
    if (idx >= total) return;
    float2 v = ((const float2*)h)[idx];
    __nv_bfloat16 h0 = __float2bfloat16(v.x), h1 = __float2bfloat16(v.y);
    __nv_bfloat16 l0 = __float2bfloat16(v.x - __bfloat162float(h0));
    __nv_bfloat16 l1 = __float2bfloat16(v.y - __bfloat162float(h1));
    ((__nv_bfloat162*)g_hb_hi)[idx] = __nv_bfloat162(h0, h1);
    ((__nv_bfloat162*)g_hb_lo)[idx] = __nv_bfloat162(l0, l1);
}

// ---------------------------------------------------------------------------
// Kernel 1: ht[m0+row][r][:] = h_tile @ W_r  (split bf16, mma.sync, 3 passes,
// single A/B smem buffer reloaded per pass via cp.async; 2 CTAs/SM).
// ---------------------------------------------------------------------------
__global__ __launch_bounds__(256, 2) void rgcn_mma_gemm() {
    extern __shared__ char smem[];
    const uint32_t raw  = smem_u32(smem);
    const uint32_t base = (raw + 1023u) & ~1023u;

    const uint32_t A_T = base;
    const uint32_t B_T = base + 32768;

    const int tid  = threadIdx.x;
    const int wid  = tid >> 5;
    const int lane = tid & 31;
    const int r    = blockIdx.x;
    const int m0   = blockIdx.y * 128;

    const int mwarp = wid & 3;
    const int nwarp = wid >> 2;

    // ldmatrix lane geometry (validated in R3)
    const int row_a = (lane & 7) + ((lane >> 3) & 1) * 8;
    const int ka    = ((lane >> 4) & 1) * 8;
    const int row_b = (lane & 7) + ((lane >> 4) & 1) * 8;
    const int kb    = ((lane >> 3) & 1) * 8;

    float acc[2][8][4];
#pragma unroll
    for (int mi = 0; mi < 2; mi++)
#pragma unroll
        for (int nj = 0; nj < 8; nj++)
#pragma unroll
            for (int q = 0; q < 4; q++) acc[mi][nj][q] = 0.0f;

    const __nv_bfloat16* A_src[3] = {g_hb_hi, g_hb_hi, g_hb_lo};
    const __nv_bfloat16* B_src[3] = {g_wb_hi + (size_t)r * FD * FD,
                                     g_wb_lo + (size_t)r * FD * FD,
                                     g_wb_hi + (size_t)r * FD * FD};

    // Per-thread load geometry: tile = 2048 chunks of 16 B; 8 chunks/thread.
    // chunk idx = tid*8 + q : row = idx >> 4 (16 chunks/row), k = (idx & 15) * 8
    for (int p = 0; p < 3; p++) {
        // --- load A tile (rows = nodes, zero-fill OOB) ---
        const __nv_bfloat16* as = A_src[p];
#pragma unroll
        for (int q = 0; q < 8; q++) {
            int idx = tid * 8 + q;
            int row = idx >> 4;
            int k   = (idx & 15) * 8;
            int n   = m0 + row;
            cpasync16(A_T + tile_off(row, k), as + (size_t)n * FD + k,
                      (n < NN) ? 16 : 0);
        }
        // --- load B tile ---
        const __nv_bfloat16* bs = B_src[p];
#pragma unroll
        for (int q = 0; q < 8; q++) {
            int idx = tid * 8 + q;
            int row = idx >> 4;
            int k   = (idx & 15) * 8;
            cpasync16(B_T + tile_off(row, k), bs + row * FD + k, 16);
        }
        CP_COMMIT();
        CP_WAIT0();
        __syncthreads();

#pragma unroll
        for (int k0 = 0; k0 < 128; k0 += 16) {
            uint32_t af[2][4];
#pragma unroll
            for (int mi = 0; mi < 2; mi++)
                ldm_x4(af[mi], A_T + tile_off(mwarp * 32 + mi * 16 + row_a, k0 + ka));
            uint32_t bf[4][4];
#pragma unroll
            for (int q = 0; q < 4; q++)
                ldm_x4(bf[q], B_T + tile_off(nwarp * 64 + q * 16 + row_b, k0 + kb));
#pragma unroll
            for (int mi = 0; mi < 2; mi++)
#pragma unroll
                for (int nj = 0; nj < 8; nj++)
                    mma_16816(acc[mi][nj], af[mi],
                              bf[nj >> 1][(nj & 1) * 2], bf[nj >> 1][(nj & 1) * 2 + 1]);
        }
        __syncthreads();
    }

    // --- Epilogue ---
    const int crow = lane >> 2;
    const int ccol = (lane & 3) * 2;
#pragma unroll
    for (int mi = 0; mi < 2; mi++) {
        int row0 = mwarp * 32 + mi * 16 + crow;
        int n0 = m0 + row0;
        int n1 = n0 + 8;
        float* d0 = g_ht + ((size_t)n0 * NR + r) * FD + nwarp * 64 + ccol;
        float* d1 = g_ht + ((size_t)n1 * NR + r) * FD + nwarp * 64 + ccol;
#pragma unroll
        for (int nj = 0; nj < 8; nj++) {
            if (n0 < NN) *(float2*)(d0 + nj * 8) = make_float2(acc[mi][nj][0], acc[mi][nj][1]);
            if (n1 < NN) *(float2*)(d1 + nj * 8) = make_float2(acc[mi][nj][2], acc[mi][nj][3]);
        }
    }
}

// ---------------------------------------------------------------------------
// Kernel 2: per-edge gather + scaled vector reduction into out[dst].
// ---------------------------------------------------------------------------
__global__ __launch_bounds__(256) void rgcn_edges(const float* __restrict__ enorm,
                                                  const int* __restrict__ etype,
                                                  const int* __restrict__ esrc,
                                                  const int* __restrict__ edst,
                                                  float* __restrict__ out) {
    const int e = blockIdx.x * 8 + (threadIdx.x >> 5);
    if (e >= NE) return;
    const int lane = threadIdx.x & 31;

    const int   s  = __ldg(esrc + e);
    const int   d  = __ldg(edst + e);
    const int   t  = __ldg(etype + e);
    const float nv = __ldg(enorm + e);

    const float4* row = (const float4*)(g_ht + ((size_t)s * NR + t) * FD);
    float4 v = row[lane];

    float* o = out + (size_t)d * FD + lane * 4;
    asm volatile("red.global.add.v4.f32 [%0], {%1, %2, %3, %4};"
                 :: "l"(o), "f"(v.x * nv), "f"(v.y * nv), "f"(v.z * nv), "f"(v.w * nv)
                 : "memory");
}

// ---------------------------------------------------------------------------
// Kernel 3: out = relu(out + bias)
// ---------------------------------------------------------------------------
__global__ __launch_bounds__(256) void rgcn_bias_relu(float* __restrict__ out,
                                                      const float* __restrict__ bias) {
    const int i = blockIdx.x * 256 + threadIdx.x;
    const int total = NN * FD / 4;
    if (i >= total) return;
    const int o = (i * 4) & (FD - 1);
    float4 v = ((float4*)out)[i];
    v.x = fmaxf(v.x + __ldg(bias + o + 0), 0.0f);
    v.y = fmaxf(v.y + __ldg(bias + o + 1), 0.0f);
    v.z = fmaxf(v.z + __ldg(bias + o + 2), 0.0f);
    v.w = fmaxf(v.w + __ldg(bias + o + 3), 0.0f);
    ((float4*)out)[i] = v;
}

extern "C" void kernel_launch(void* const* d_in, const int* in_sizes, int n_in,
                              void* d_out, int out_size) {
    const float* h     = (const float*)d_in[0];
    const float* enorm = (const float*)d_in[1];
    const int*   etype = (const int*)d_in[2];
    const int*   esrc  = (const int*)d_in[3];
    const int*   edst  = (const int*)d_in[4];
    const float* w     = (const float*)d_in[5];
    const float* bias  = (const float*)d_in[6];
    float* out = (float*)d_out;

    cudaFuncSetAttribute(rgcn_mma_gemm, cudaFuncAttributeMaxDynamicSharedMemorySize,
                         SMEM_BYTES);

    cudaMemsetAsync(out, 0, (size_t)NN * FD * sizeof(float), 0);

    rgcn_wprep<<<(NR * FD * FD + 255) / 256, 256>>>(w);
    rgcn_hprep<<<(NN * FD / 2 + 255) / 256, 256>>>(h);

    dim3 gg(NR, M_TILES);
    rgcn_mma_gemm<<<gg, 256, SMEM_BYTES>>>();

    rgcn_edges<<<(NE + 7) / 8, 256>>>(enorm, etype, esrc, edst, out);

    rgcn_bias_relu<<<(NN * FD / 4 + 255) / 256, 256>>>(out, bias);
}

// round 6
// speedup vs baseline: 1.5662x; 1.1608x over previous
#include <cuda_runtime.h>
#include <cuda_bf16.h>
#include <cuda_fp16.h>
#include <cstdint>

#define NN 50000
#define NE 800000
#define NR 8
#define FD 128

#define M_TILES ((NN + 127) / 128)        // 391
#define SMEM_BYTES (1024 + 3 * 32768)     // align slack + A + Bhi + Blo = 99328

// Scratch: ht[n][r][o] fp16, 102.4 MB (fits L2).
__device__ __half g_ht[(size_t)NN * NR * FD];
// W transposed + bf16-split: [r][o][i]
__device__ __nv_bfloat16 g_wb_hi[NR * FD * FD];
__device__ __nv_bfloat16 g_wb_lo[NR * FD * FD];
// h bf16-split: [n][i]
__device__ __nv_bfloat16 g_hb_hi[(size_t)NN * FD];
__device__ __nv_bfloat16 g_hb_lo[(size_t)NN * FD];

// ---------------------------------------------------------------------------
__device__ __forceinline__ uint32_t smem_u32(const void* p) {
    uint32_t a;
    asm("{ .reg .u64 t; cvta.to.shared.u64 t, %1; cvt.u32.u64 %0, t; }" : "=r"(a) : "l"(p));
    return a;
}

// Blocked SW128 K-major layout for a [128 rows x 128 bf16] tile.
__device__ __forceinline__ uint32_t tile_off(int row, int k) {
    uint32_t b = ((uint32_t)(row >> 3) + (uint32_t)(k >> 6) * 16u) * 1024u
               + (uint32_t)(row & 7) * 128u + (uint32_t)(k & 63) * 2u;
    return b ^ ((b >> 3) & 0x70u);
}

__device__ __forceinline__ void ldm_x4(uint32_t* r, uint32_t addr) {
    asm volatile("ldmatrix.sync.aligned.m8n8.x4.shared.b16 {%0,%1,%2,%3}, [%4];"
                 : "=r"(r[0]), "=r"(r[1]), "=r"(r[2]), "=r"(r[3]) : "r"(addr));
}

__device__ __forceinline__ void mma_16816(float* c, const uint32_t* a,
                                          uint32_t b0, uint32_t b1) {
    asm volatile(
        "mma.sync.aligned.m16n8k16.row.col.f32.bf16.bf16.f32 "
        "{%0,%1,%2,%3}, {%4,%5,%6,%7}, {%8,%9}, {%0,%1,%2,%3};"
        : "+f"(c[0]), "+f"(c[1]), "+f"(c[2]), "+f"(c[3])
        : "r"(a[0]), "r"(a[1]), "r"(a[2]), "r"(a[3]), "r"(b0), "r"(b1));
}

__device__ __forceinline__ void cpasync16(uint32_t dst, const void* src, int sz) {
    asm volatile("cp.async.cg.shared.global [%0], [%1], 16, %2;"
                 :: "r"(dst), "l"(src), "r"(sz) : "memory");
}
#define CP_COMMIT() asm volatile("cp.async.commit_group;" ::: "memory")
#define CP_WAIT0()  asm volatile("cp.async.wait_group 0;" ::: "memory")

// ---------------------------------------------------------------------------
// Kernel 0a: split W into bf16 hi/lo, transposed to [r][o][i].
// ---------------------------------------------------------------------------
__global__ __launch_bounds__(256) void rgcn_wprep(const float* __restrict__ w) {
    int idx = blockIdx.x * 256 + threadIdx.x;
    if (idx >= NR * FD * FD) return;
    int r = idx >> 14, rem = idx & 16383;
    int o = rem >> 7, i = rem & 127;
    float x = w[((size_t)r * FD + i) * FD + o];
    __nv_bfloat16 hi = __float2bfloat16(x);
    __nv_bfloat16 lo = __float2bfloat16(x - __bfloat162float(hi));
    g_wb_hi[idx] = hi;
    g_wb_lo[idx] = lo;
}

// ---------------------------------------------------------------------------
// Kernel 0b: split h into bf16 hi/lo.
// ---------------------------------------------------------------------------
__global__ __launch_bounds__(256) void rgcn_hprep(const float* __restrict__ h) {
    int idx = blockIdx.x * 256 + threadIdx.x;        // float2 granule
    const int total = NN * FD / 2;
    if (idx >= total) return;
    float2 v = ((const float2*)h)[idx];
    __nv_bfloat16 h0 = __float2bfloat16(v.x), h1 = __float2bfloat16(v.y);
    __nv_bfloat16 l0 = __float2bfloat16(v.x - __bfloat162float(h0));
    __nv_bfloat16 l1 = __float2bfloat16(v.y - __bfloat162float(h1));
    ((__nv_bfloat162*)g_hb_hi)[idx] = __nv_bfloat162(h0, h1);
    ((__nv_bfloat162*)g_hb_lo)[idx] = __nv_bfloat162(l0, l1);
}

// ---------------------------------------------------------------------------
// Kernel 1: ht[m0+row][r][:] = h_tile @ W_r  (split bf16, mma.sync).
// Phase 1: load {A_hi, B_hi, B_lo}; fused k-loop does Ahi*Bhi + Ahi*Blo.
// Phase 2: reload A with A_lo; k-loop does Alo*Bhi. 2 CTAs/SM.
// ---------------------------------------------------------------------------
__global__ __launch_bounds__(256, 2) void rgcn_mma_gemm() {
    extern __shared__ char smem[];
    const uint32_t raw  = smem_u32(smem);
    const uint32_t base = (raw + 1023u) & ~1023u;

    const uint32_t A_T  = base;
    const uint32_t BH_T = base + 32768;
    const uint32_t BL_T = base + 65536;

    const int tid  = threadIdx.x;
    const int wid  = tid >> 5;
    const int lane = tid & 31;
    const int r    = blockIdx.x;
    const int m0   = blockIdx.y * 128;

    const int mwarp = wid & 3;
    const int nwarp = wid >> 2;

    // ldmatrix lane geometry (validated in R3/R5)
    const int row_a = (lane & 7) + ((lane >> 3) & 1) * 8;
    const int ka    = ((lane >> 4) & 1) * 8;
    const int row_b = (lane & 7) + ((lane >> 4) & 1) * 8;
    const int kb    = ((lane >> 3) & 1) * 8;

    float acc[2][8][4];
#pragma unroll
    for (int mi = 0; mi < 2; mi++)
#pragma unroll
        for (int nj = 0; nj < 8; nj++)
#pragma unroll
            for (int q = 0; q < 4; q++) acc[mi][nj][q] = 0.0f;

    const __nv_bfloat16* wbh = g_wb_hi + (size_t)r * FD * FD;
    const __nv_bfloat16* wbl = g_wb_lo + (size_t)r * FD * FD;

    // Per-thread load geometry: tile = 2048 x 16B chunks; 8 chunks/thread.
    // chunk idx = tid*8 + q : row = idx >> 4, k = (idx & 15) * 8
#pragma unroll
    for (int q = 0; q < 8; q++) {
        int idx = tid * 8 + q;
        int row = idx >> 4;
        int k   = (idx & 15) * 8;
        int n   = m0 + row;
        cpasync16(A_T + tile_off(row, k), g_hb_hi + (size_t)n * FD + k,
                  (n < NN) ? 16 : 0);
        cpasync16(BH_T + tile_off(row, k), wbh + row * FD + k, 16);
        cpasync16(BL_T + tile_off(row, k), wbl + row * FD + k, 16);
    }
    CP_COMMIT();
    CP_WAIT0();
    __syncthreads();

    // --- Pass 1+2 fused: Ahi*Bhi + Ahi*Blo ---
#pragma unroll
    for (int k0 = 0; k0 < 128; k0 += 16) {
        uint32_t af[2][4];
#pragma unroll
        for (int mi = 0; mi < 2; mi++)
            ldm_x4(af[mi], A_T + tile_off(mwarp * 32 + mi * 16 + row_a, k0 + ka));
        uint32_t bh[4][4], bl[4][4];
#pragma unroll
        for (int q = 0; q < 4; q++) {
            uint32_t boff = tile_off(nwarp * 64 + q * 16 + row_b, k0 + kb);
            ldm_x4(bh[q], BH_T + boff);
            ldm_x4(bl[q], BL_T + boff);
        }
#pragma unroll
        for (int mi = 0; mi < 2; mi++)
#pragma unroll
            for (int nj = 0; nj < 8; nj++) {
                mma_16816(acc[mi][nj], af[mi],
                          bh[nj >> 1][(nj & 1) * 2], bh[nj >> 1][(nj & 1) * 2 + 1]);
                mma_16816(acc[mi][nj], af[mi],
                          bl[nj >> 1][(nj & 1) * 2], bl[nj >> 1][(nj & 1) * 2 + 1]);
            }
    }
    __syncthreads();

    // --- Reload A with A_lo ---
#pragma unroll
    for (int q = 0; q < 8; q++) {
        int idx = tid * 8 + q;
        int row = idx >> 4;
        int k   = (idx & 15) * 8;
        int n   = m0 + row;
        cpasync16(A_T + tile_off(row, k), g_hb_lo + (size_t)n * FD + k,
                  (n < NN) ? 16 : 0);
    }
    CP_COMMIT();
    CP_WAIT0();
    __syncthreads();

    // --- Pass 3: Alo*Bhi ---
#pragma unroll
    for (int k0 = 0; k0 < 128; k0 += 16) {
        uint32_t af[2][4];
#pragma unroll
        for (int mi = 0; mi < 2; mi++)
            ldm_x4(af[mi], A_T + tile_off(mwarp * 32 + mi * 16 + row_a, k0 + ka));
        uint32_t bh[4][4];
#pragma unroll
        for (int q = 0; q < 4; q++)
            ldm_x4(bh[q], BH_T + tile_off(nwarp * 64 + q * 16 + row_b, k0 + kb));
#pragma unroll
        for (int mi = 0; mi < 2; mi++)
#pragma unroll
            for (int nj = 0; nj < 8; nj++)
                mma_16816(acc[mi][nj], af[mi],
                          bh[nj >> 1][(nj & 1) * 2], bh[nj >> 1][(nj & 1) * 2 + 1]);
    }

    // --- Epilogue: fp16 stores ---
    const int crow = lane >> 2;
    const int ccol = (lane & 3) * 2;
#pragma unroll
    for (int mi = 0; mi < 2; mi++) {
        int row0 = mwarp * 32 + mi * 16 + crow;
        int n0 = m0 + row0;
        int n1 = n0 + 8;
        __half* d0 = g_ht + ((size_t)n0 * NR + r) * FD + nwarp * 64 + ccol;
        __half* d1 = g_ht + ((size_t)n1 * NR + r) * FD + nwarp * 64 + ccol;
#pragma unroll
        for (int nj = 0; nj < 8; nj++) {
            if (n0 < NN) *(__half2*)(d0 + nj * 8) = __floats2half2_rn(acc[mi][nj][0], acc[mi][nj][1]);
            if (n1 < NN) *(__half2*)(d1 + nj * 8) = __floats2half2_rn(acc[mi][nj][2], acc[mi][nj][3]);
        }
    }
}

// ---------------------------------------------------------------------------
// Kernel 2: per-edge gather (fp16 rows) + scaled fp32 reduction into out[dst].
// One warp per edge; lane l handles floats [4l, 4l+4) (8 B fp16 per lane).
// ---------------------------------------------------------------------------
__global__ __launch_bounds__(256) void rgcn_edges(const float* __restrict__ enorm,
                                                  const int* __restrict__ etype,
                                                  const int* __restrict__ esrc,
                                                  const int* __restrict__ edst,
                                                  float* __restrict__ out) {
    const int e = blockIdx.x * 8 + (threadIdx.x >> 5);
    if (e >= NE) return;
    const int lane = threadIdx.x & 31;

    const int   s  = __ldg(esrc + e);
    const int   d  = __ldg(edst + e);
    const int   t  = __ldg(etype + e);
    const float nv = __ldg(enorm + e);

    const uint2* row = (const uint2*)(g_ht + ((size_t)s * NR + t) * FD);
    uint2 rawv = row[lane];
    float2 f0 = __half22float2(*(__half2*)&rawv.x);
    float2 f1 = __half22float2(*(__half2*)&rawv.y);

    float* o = out + (size_t)d * FD + lane * 4;
    asm volatile("red.global.add.v4.f32 [%0], {%1, %2, %3, %4};"
                 :: "l"(o), "f"(f0.x * nv), "f"(f0.y * nv), "f"(f1.x * nv), "f"(f1.y * nv)
                 : "memory");
}

// ---------------------------------------------------------------------------
// Kernel 3: out = relu(out + bias)
// ---------------------------------------------------------------------------
__global__ __launch_bounds__(256) void rgcn_bias_relu(float* __restrict__ out,
                                                      const float* __restrict__ bias) {
    const int i = blockIdx.x * 256 + threadIdx.x;
    const int total = NN * FD / 4;
    if (i >= total) return;
    const int o = (i * 4) & (FD - 1);
    float4 v = ((float4*)out)[i];
    v.x = fmaxf(v.x + __ldg(bias + o + 0), 0.0f);
    v.y = fmaxf(v.y + __ldg(bias + o + 1), 0.0f);
    v.z = fmaxf(v.z + __ldg(bias + o + 2), 0.0f);
    v.w = fmaxf(v.w + __ldg(bias + o + 3), 0.0f);
    ((float4*)out)[i] = v;
}

extern "C" void kernel_launch(void* const* d_in, const int* in_sizes, int n_in,
                              void* d_out, int out_size) {
    const float* h     = (const float*)d_in[0];
    const float* enorm = (const float*)d_in[1];
    const int*   etype = (const int*)d_in[2];
    const int*   esrc  = (const int*)d_in[3];
    const int*   edst  = (const int*)d_in[4];
    const float* w     = (const float*)d_in[5];
    const float* bias  = (const float*)d_in[6];
    float* out = (float*)d_out;

    cudaFuncSetAttribute(rgcn_mma_gemm, cudaFuncAttributeMaxDynamicSharedMemorySize,
                         SMEM_BYTES);

    cudaMemsetAsync(out, 0, (size_t)NN * FD * sizeof(float), 0);

    rgcn_wprep<<<(NR * FD * FD + 255) / 256, 256>>>(w);
    rgcn_hprep<<<(NN * FD / 2 + 255) / 256, 256>>>(h);

    dim3 gg(NR, M_TILES);
    rgcn_mma_gemm<<<gg, 256, SMEM_BYTES>>>();

    rgcn_edges<<<(NE + 7) / 8, 256>>>(enorm, etype, esrc, edst, out);

    rgcn_bias_relu<<<(NN * FD / 4 + 255) / 256, 256>>>(out, bias);
}

// round 9
// speedup vs baseline: 1.7495x; 1.1170x over previous
#include <cuda_runtime.h>
#include <cuda_bf16.h>
#include <cuda_fp16.h>
#include <cstdint>

#define NN 50000
#define NE 800000
#define NR 8
#define FD 128

#define M_TILES ((NN + 127) / 128)        // 391
#define SMEM_BYTES (1024 + 3 * 32768)     // align slack + A + Bhi + Blo = 99328

// Scratch: ht[n][r][o] fp16, 102.4 MB (fits L2).
__device__ __half g_ht[(size_t)NN * NR * FD];
// W transposed + bf16-split: [r][o][i]
__device__ __nv_bfloat16 g_wb_hi[NR * FD * FD];
__device__ __nv_bfloat16 g_wb_lo[NR * FD * FD];
// h bf16-split: [n][i]
__device__ __nv_bfloat16 g_hb_hi[(size_t)NN * FD];
__device__ __nv_bfloat16 g_hb_lo[(size_t)NN * FD];
// dst-CSR scratch
__device__ int  g_counts[NN];
__device__ int  g_offs[NN + 1];
__device__ int  g_cursor[NN];
__device__ int2 g_epack[NE];              // {src*NR+type, norm bits}

// ---------------------------------------------------------------------------
__device__ __forceinline__ uint32_t smem_u32(const void* p) {
    uint32_t a;
    asm("{ .reg .u64 t; cvta.to.shared.u64 t, %1; cvt.u32.u64 %0, t; }" : "=r"(a) : "l"(p));
    return a;
}

// Blocked SW128 K-major layout for a [128 rows x 128 bf16] tile.
__device__ __forceinline__ uint32_t tile_off(int row, int k) {
    uint32_t b = ((uint32_t)(row >> 3) + (uint32_t)(k >> 6) * 16u) * 1024u
               + (uint32_t)(row & 7) * 128u + (uint32_t)(k & 63) * 2u;
    return b ^ ((b >> 3) & 0x70u);
}

__device__ __forceinline__ void ldm_x4(uint32_t* r, uint32_t addr) {
    asm volatile("ldmatrix.sync.aligned.m8n8.x4.shared.b16 {%0,%1,%2,%3}, [%4];"
                 : "=r"(r[0]), "=r"(r[1]), "=r"(r[2]), "=r"(r[3]) : "r"(addr));
}

__device__ __forceinline__ void mma_16816(float* c, const uint32_t* a,
                                          uint32_t b0, uint32_t b1) {
    asm volatile(
        "mma.sync.aligned.m16n8k16.row.col.f32.bf16.bf16.f32 "
        "{%0,%1,%2,%3}, {%4,%5,%6,%7}, {%8,%9}, {%0,%1,%2,%3};"
        : "+f"(c[0]), "+f"(c[1]), "+f"(c[2]), "+f"(c[3])
        : "r"(a[0]), "r"(a[1]), "r"(a[2]), "r"(a[3]), "r"(b0), "r"(b1));
}

__device__ __forceinline__ void cpasync16(uint32_t dst, const void* src, int sz) {
    asm volatile("cp.async.cg.shared.global [%0], [%1], 16, %2;"
                 :: "r"(dst), "l"(src), "r"(sz) : "memory");
}
#define CP_COMMIT() asm volatile("cp.async.commit_group;" ::: "memory")
#define CP_WAIT0()  asm volatile("cp.async.wait_group 0;" ::: "memory")

// ---------------------------------------------------------------------------
// Kernel 0a: split W into bf16 hi/lo, transposed to [r][o][i].
// ---------------------------------------------------------------------------
__global__ __launch_bounds__(256) void rgcn_wprep(const float* __restrict__ w) {
    int idx = blockIdx.x * 256 + threadIdx.x;
    if (idx >= NR * FD * FD) return;
    int r = idx >> 14, rem = idx & 16383;
    int o = rem >> 7, i = rem & 127;
    float x = w[((size_t)r * FD + i) * FD + o];
    __nv_bfloat16 hi = __float2bfloat16(x);
    __nv_bfloat16 lo = __float2bfloat16(x - __bfloat162float(hi));
    g_wb_hi[idx] = hi;
    g_wb_lo[idx] = lo;
}

// ---------------------------------------------------------------------------
// Kernel 0b: split h into bf16 hi/lo.
// ---------------------------------------------------------------------------
__global__ __launch_bounds__(256) void rgcn_hprep(const float* __restrict__ h) {
    int idx = blockIdx.x * 256 + threadIdx.x;        // float2 granule
    const int total = NN * FD / 2;
    if (idx >= total) return;
    float2 v = ((const float2*)h)[idx];
    __nv_bfloat16 h0 = __float2bfloat16(v.x), h1 = __float2bfloat16(v.y);
    __nv_bfloat16 l0 = __float2bfloat16(v.x - __bfloat162float(h0));
    __nv_bfloat16 l1 = __float2bfloat16(v.y - __bfloat162float(h1));
    ((__nv_bfloat162*)g_hb_hi)[idx] = __nv_bfloat162(h0, h1);
    ((__nv_bfloat162*)g_hb_lo)[idx] = __nv_bfloat162(l0, l1);
}

// ---------------------------------------------------------------------------
// CSR build: histogram -> scan -> scatter (dst-ordered packed edges).
// ---------------------------------------------------------------------------
__global__ __launch_bounds__(256) void rgcn_hist(const int* __restrict__ edst) {
    int e = blockIdx.x * 256 + threadIdx.x;
    if (e < NE) atomicAdd(&g_counts[__ldg(edst + e)], 1);
}

__global__ __launch_bounds__(1024) void rgcn_scan() {
    const int tid = threadIdx.x, lane = tid & 31, w = tid >> 5;  // 32 warps
    __shared__ int wsum[32];
    __shared__ int chunk_carry;
    if (tid == 0) chunk_carry = 0;
    __syncthreads();
    for (int c0 = 0; c0 < NN; c0 += 4096) {
        int i0 = c0 + tid * 4;
        int v[4], s = 0;
#pragma unroll
        for (int q = 0; q < 4; q++) {
            int i = i0 + q;
            v[q] = (i < NN) ? g_counts[i] : 0;
            s += v[q];
        }
        int incl = s;
#pragma unroll
        for (int off = 1; off < 32; off <<= 1) {
            int t = __shfl_up_sync(~0u, incl, off);
            if (lane >= off) incl += t;
        }
        if (lane == 31) wsum[w] = incl;
        __syncthreads();
        if (w == 0) {
            int x = wsum[lane];
#pragma unroll
            for (int off = 1; off < 32; off <<= 1) {
                int t = __shfl_up_sync(~0u, x, off);
                if (lane >= off) x += t;
            }
            wsum[lane] = x;
        }
        __syncthreads();
        int run = chunk_carry + (w ? wsum[w - 1] : 0) + incl - s;
#pragma unroll
        for (int q = 0; q < 4; q++) {
            int i = i0 + q;
            if (i < NN) { g_offs[i] = run; g_cursor[i] = run; }
            run += v[q];
        }
        __syncthreads();
        if (tid == 0) chunk_carry += wsum[31];
        __syncthreads();
    }
    if (tid == 0) g_offs[NN] = chunk_carry;
}

__global__ __launch_bounds__(256) void rgcn_scatter(const int* __restrict__ esrc,
                                                    const int* __restrict__ etype,
                                                    const float* __restrict__ enorm,
                                                    const int* __restrict__ edst) {
    int e = blockIdx.x * 256 + threadIdx.x;
    if (e >= NE) return;
    int d = __ldg(edst + e);
    int pos = atomicAdd(&g_cursor[d], 1);
    g_epack[pos] = make_int2(__ldg(esrc + e) * NR + __ldg(etype + e),
                             __float_as_int(__ldg(enorm + e)));
}

// ---------------------------------------------------------------------------
// Kernel 1: ht[m0+row][r][:] = h_tile @ W_r  (split bf16, mma.sync).
// Phase 1: load {A_hi, B_hi, B_lo}; fused k-loop does Ahi*Bhi + Ahi*Blo.
// Phase 2: reload A with A_lo; k-loop does Alo*Bhi. 2 CTAs/SM.
// ---------------------------------------------------------------------------
__global__ __launch_bounds__(256, 2) void rgcn_mma_gemm() {
    extern __shared__ char smem[];
    const uint32_t raw  = smem_u32(smem);
    const uint32_t base = (raw + 1023u) & ~1023u;

    const uint32_t A_T  = base;
    const uint32_t BH_T = base + 32768;
    const uint32_t BL_T = base + 65536;

    const int tid  = threadIdx.x;
    const int wid  = tid >> 5;
    const int lane = tid & 31;
    const int r    = blockIdx.x;
    const int m0   = blockIdx.y * 128;

    const int mwarp = wid & 3;
    const int nwarp = wid >> 2;

    const int row_a = (lane & 7) + ((lane >> 3) & 1) * 8;
    const int ka    = ((lane >> 4) & 1) * 8;
    const int row_b = (lane & 7) + ((lane >> 4) & 1) * 8;
    const int kb    = ((lane >> 3) & 1) * 8;

    float acc[2][8][4];
#pragma unroll
    for (int mi = 0; mi < 2; mi++)
#pragma unroll
        for (int nj = 0; nj < 8; nj++)
#pragma unroll
            for (int q = 0; q < 4; q++) acc[mi][nj][q] = 0.0f;

    const __nv_bfloat16* wbh = g_wb_hi + (size_t)r * FD * FD;
    const __nv_bfloat16* wbl = g_wb_lo + (size_t)r * FD * FD;

#pragma unroll
    for (int q = 0; q < 8; q++) {
        int idx = tid * 8 + q;
        int row = idx >> 4;
        int k   = (idx & 15) * 8;
        int n   = m0 + row;
        cpasync16(A_T + tile_off(row, k), g_hb_hi + (size_t)n * FD + k,
                  (n < NN) ? 16 : 0);
        cpasync16(BH_T + tile_off(row, k), wbh + row * FD + k, 16);
        cpasync16(BL_T + tile_off(row, k), wbl + row * FD + k, 16);
    }
    CP_COMMIT();
    CP_WAIT0();
    __syncthreads();

    // --- Pass 1+2 fused: Ahi*Bhi + Ahi*Blo ---
#pragma unroll
    for (int k0 = 0; k0 < 128; k0 += 16) {
        uint32_t af[2][4];
#pragma unroll
        for (int mi = 0; mi < 2; mi++)
            ldm_x4(af[mi], A_T + tile_off(mwarp * 32 + mi * 16 + row_a, k0 + ka));
        uint32_t bh[4][4], bl[4][4];
#pragma unroll
        for (int q = 0; q < 4; q++) {
            uint32_t boff = tile_off(nwarp * 64 + q * 16 + row_b, k0 + kb);
            ldm_x4(bh[q], BH_T + boff);
            ldm_x4(bl[q], BL_T + boff);
        }
#pragma unroll
        for (int mi = 0; mi < 2; mi++)
#pragma unroll
            for (int nj = 0; nj < 8; nj++) {
                mma_16816(acc[mi][nj], af[mi],
                          bh[nj >> 1][(nj & 1) * 2], bh[nj >> 1][(nj & 1) * 2 + 1]);
                mma_16816(acc[mi][nj], af[mi],
                          bl[nj >> 1][(nj & 1) * 2], bl[nj >> 1][(nj & 1) * 2 + 1]);
            }
    }
    __syncthreads();

    // --- Reload A with A_lo ---
#pragma unroll
    for (int q = 0; q < 8; q++) {
        int idx = tid * 8 + q;
        int row = idx >> 4;
        int k   = (idx & 15) * 8;
        int n   = m0 + row;
        cpasync16(A_T + tile_off(row, k), g_hb_lo + (size_t)n * FD + k,
                  (n < NN) ? 16 : 0);
    }
    CP_COMMIT();
    CP_WAIT0();
    __syncthreads();

    // --- Pass 3: Alo*Bhi ---
#pragma unroll
    for (int k0 = 0; k0 < 128; k0 += 16) {
        uint32_t af[2][4];
#pragma unroll
        for (int mi = 0; mi < 2; mi++)
            ldm_x4(af[mi], A_T + tile_off(mwarp * 32 + mi * 16 + row_a, k0 + ka));
        uint32_t bh[4][4];
#pragma unroll
        for (int q = 0; q < 4; q++)
            ldm_x4(bh[q], BH_T + tile_off(nwarp * 64 + q * 16 + row_b, k0 + kb));
#pragma unroll
        for (int mi = 0; mi < 2; mi++)
#pragma unroll
            for (int nj = 0; nj < 8; nj++)
                mma_16816(acc[mi][nj], af[mi],
                          bh[nj >> 1][(nj & 1) * 2], bh[nj >> 1][(nj & 1) * 2 + 1]);
    }

    // --- Epilogue: fp16 stores ---
    const int crow = lane >> 2;
    const int ccol = (lane & 3) * 2;
#pragma unroll
    for (int mi = 0; mi < 2; mi++) {
        int row0 = mwarp * 32 + mi * 16 + crow;
        int n0 = m0 + row0;
        int n1 = n0 + 8;
        __half* d0 = g_ht + ((size_t)n0 * NR + r) * FD + nwarp * 64 + ccol;
        __half* d1 = g_ht + ((size_t)n1 * NR + r) * FD + nwarp * 64 + ccol;
#pragma unroll
        for (int nj = 0; nj < 8; nj++) {
            if (n0 < NN) *(__half2*)(d0 + nj * 8) = __floats2half2_rn(acc[mi][nj][0], acc[mi][nj][1]);
            if (n1 < NN) *(__half2*)(d1 + nj * 8) = __floats2half2_rn(acc[mi][nj][2], acc[mi][nj][3]);
        }
    }
}

// ---------------------------------------------------------------------------
// Kernel 2: per-node aggregation over dst-CSR + bias + relu, plain stores.
// One warp per node; lane l owns floats [4l, 4l+4).
// ---------------------------------------------------------------------------
__global__ __launch_bounds__(256) void rgcn_agg(const float* __restrict__ bias,
                                                float* __restrict__ out) {
    const int n = blockIdx.x * 8 + (threadIdx.x >> 5);
    if (n >= NN) return;
    const int lane = threadIdx.x & 31;

    const int beg = __ldg(&g_offs[n]);
    const int end = __ldg(&g_offs[n + 1]);

    float a0 = 0.f, a1 = 0.f, a2 = 0.f, a3 = 0.f;

    int i = beg;
    if (i < end) {
        int2 p = __ldg(&g_epack[i]);
        while (true) {
            int2 cur = p;
            if (i + 1 < end) p = __ldg(&g_epack[i + 1]);
            float nv = __int_as_float(cur.y);
            uint2 rawv = __ldg((const uint2*)(g_ht + (size_t)cur.x * FD) + lane);
            float2 f0 = __half22float2(*(__half2*)&rawv.x);
            float2 f1 = __half22float2(*(__half2*)&rawv.y);
            a0 = fmaf(nv, f0.x, a0);
            a1 = fmaf(nv, f0.y, a1);
            a2 = fmaf(nv, f1.x, a2);
            a3 = fmaf(nv, f1.y, a3);
            if (++i >= end) break;
        }
    }

    float4 b = __ldg((const float4*)bias + lane);
    float4 o;
    o.x = fmaxf(a0 + b.x, 0.0f);
    o.y = fmaxf(a1 + b.y, 0.0f);
    o.z = fmaxf(a2 + b.z, 0.0f);
    o.w = fmaxf(a3 + b.w, 0.0f);
    *(float4*)(out + (size_t)n * FD + lane * 4) = o;
}

extern "C" void kernel_launch(void* const* d_in, const int* in_sizes, int n_in,
                              void* d_out, int out_size) {
    const float* h     = (const float*)d_in[0];
    const float* enorm = (const float*)d_in[1];
    const int*   etype = (const int*)d_in[2];
    const int*   esrc  = (const int*)d_in[3];
    const int*   edst  = (const int*)d_in[4];
    const float* w     = (const float*)d_in[5];
    const float* bias  = (const float*)d_in[6];
    float* out = (float*)d_out;

    cudaFuncSetAttribute(rgcn_mma_gemm, cudaFuncAttributeMaxDynamicSharedMemorySize,
                         SMEM_BYTES);

    // zero CSR counters
    void* cptr = nullptr;
    cudaGetSymbolAddress(&cptr, g_counts);
    cudaMemsetAsync(cptr, 0, NN * sizeof(int), 0);

    rgcn_wprep<<<(NR * FD * FD + 255) / 256, 256>>>(w);
    rgcn_hprep<<<(NN * FD / 2 + 255) / 256, 256>>>(h);

    rgcn_hist<<<(NE + 255) / 256, 256>>>(edst);
    rgcn_scan<<<1, 1024>>>();
    rgcn_scatter<<<(NE + 255) / 256, 256>>>(esrc, etype, enorm, edst);

    dim3 gg(NR, M_TILES);
    rgcn_mma_gemm<<<gg, 256, SMEM_BYTES>>>();

    rgcn_agg<<<(NN + 7) / 8, 256>>>(bias, out);
}

// round 10
// speedup vs baseline: 3.0256x; 1.7295x over previous
#include <cuda_runtime.h>
#include <cuda_fp16.h>
#include <cstdint>

#define NN 50000
#define NE 800000
#define NR 8
#define FD 128

#define M_TILES ((NN + 127) / 128)        // 391
#define SMEM_BYTES (1024 + 2 * 32768)     // align slack + A + B = 66560
#define SCAN_B ((NN + 4095) / 4096)       // 13

// Scratch: ht[n][r][o] fp16, 102.4 MB (fits L2).
__device__ __half g_ht[(size_t)NN * NR * FD];
// W fp16 transposed: [r][o][i]
__device__ __half g_wf[NR * FD * FD];
// h fp16: [n][i]
__device__ __half g_hf[(size_t)NN * FD];
// dst-CSR scratch
__device__ int  g_counts[NN];
__device__ int  g_offs[NN + 1];
__device__ int  g_cursor[NN];
__device__ int  g_part[32];
__device__ int  g_partoff[32];
__device__ int2 g_epack[NE];              // {src*NR+type, norm bits}

// ---------------------------------------------------------------------------
__device__ __forceinline__ uint32_t smem_u32(const void* p) {
    uint32_t a;
    asm("{ .reg .u64 t; cvta.to.shared.u64 t, %1; cvt.u32.u64 %0, t; }" : "=r"(a) : "l"(p));
    return a;
}

// Blocked SW128 K-major layout for a [128 rows x 128 fp16] tile.
__device__ __forceinline__ uint32_t tile_off(int row, int k) {
    uint32_t b = ((uint32_t)(row >> 3) + (uint32_t)(k >> 6) * 16u) * 1024u
               + (uint32_t)(row & 7) * 128u + (uint32_t)(k & 63) * 2u;
    return b ^ ((b >> 3) & 0x70u);
}

__device__ __forceinline__ void ldm_x4(uint32_t* r, uint32_t addr) {
    asm volatile("ldmatrix.sync.aligned.m8n8.x4.shared.b16 {%0,%1,%2,%3}, [%4];"
                 : "=r"(r[0]), "=r"(r[1]), "=r"(r[2]), "=r"(r[3]) : "r"(addr));
}

__device__ __forceinline__ void mma_16816(float* c, const uint32_t* a,
                                          uint32_t b0, uint32_t b1) {
    asm volatile(
        "mma.sync.aligned.m16n8k16.row.col.f32.f16.f16.f32 "
        "{%0,%1,%2,%3}, {%4,%5,%6,%7}, {%8,%9}, {%0,%1,%2,%3};"
        : "+f"(c[0]), "+f"(c[1]), "+f"(c[2]), "+f"(c[3])
        : "r"(a[0]), "r"(a[1]), "r"(a[2]), "r"(a[3]), "r"(b0), "r"(b1));
}

__device__ __forceinline__ void cpasync16(uint32_t dst, const void* src, int sz) {
    asm volatile("cp.async.cg.shared.global [%0], [%1], 16, %2;"
                 :: "r"(dst), "l"(src), "r"(sz) : "memory");
}
#define CP_COMMIT() asm volatile("cp.async.commit_group;" ::: "memory")
#define CP_WAIT0()  asm volatile("cp.async.wait_group 0;" ::: "memory")

// ---------------------------------------------------------------------------
// Kernel 0a: W fp32 [r][i][o] -> fp16 transposed [r][o][i].
// ---------------------------------------------------------------------------
__global__ __launch_bounds__(256) void rgcn_wprep(const float* __restrict__ w) {
    int idx = blockIdx.x * 256 + threadIdx.x;
    if (idx >= NR * FD * FD) return;
    int r = idx >> 14, rem = idx & 16383;
    int o = rem >> 7, i = rem & 127;
    g_wf[idx] = __float2half_rn(w[((size_t)r * FD + i) * FD + o]);
}

// ---------------------------------------------------------------------------
// Kernel 0b: h fp32 -> fp16.
// ---------------------------------------------------------------------------
__global__ __launch_bounds__(256) void rgcn_hprep(const float* __restrict__ h) {
    int idx = blockIdx.x * 256 + threadIdx.x;        // float2 granule
    const int total = NN * FD / 2;
    if (idx >= total) return;
    float2 v = ((const float2*)h)[idx];
    ((__half2*)g_hf)[idx] = __floats2half2_rn(v.x, v.y);
}

// ---------------------------------------------------------------------------
// CSR build: histogram -> 3-stage parallel scan -> scatter.
// ---------------------------------------------------------------------------
__global__ __launch_bounds__(256) void rgcn_hist(const int* __restrict__ edst) {
    int e = blockIdx.x * 256 + threadIdx.x;
    if (e < NE) atomicAdd(&g_counts[__ldg(edst + e)], 1);
}

// Stage 1: per-block (4096 elems) sums -> g_part[blockIdx].
__global__ __launch_bounds__(1024) void rgcn_scan_part() {
    const int tid = threadIdx.x, lane = tid & 31, w = tid >> 5;
    __shared__ int ws[32];
    int i0 = blockIdx.x * 4096 + tid * 4;
    int s = 0;
#pragma unroll
    for (int q = 0; q < 4; q++) {
        int i = i0 + q;
        if (i < NN) s += g_counts[i];
    }
#pragma unroll
    for (int off = 16; off; off >>= 1) s += __shfl_down_sync(~0u, s, off);
    if (lane == 0) ws[w] = s;
    __syncthreads();
    if (w == 0) {
        int x = ws[lane];
#pragma unroll
        for (int off = 16; off; off >>= 1) x += __shfl_down_sync(~0u, x, off);
        if (lane == 0) g_part[blockIdx.x] = x;
    }
}

// Stage 2: 1-warp scan of SCAN_B partials -> g_partoff (exclusive), total -> g_offs[NN].
__global__ void rgcn_scan_mid() {
    int lane = threadIdx.x;
    int v = (lane < SCAN_B) ? g_part[lane] : 0;
    int incl = v;
#pragma unroll
    for (int off = 1; off < 32; off <<= 1) {
        int t = __shfl_up_sync(~0u, incl, off);
        if (lane >= off) incl += t;
    }
    if (lane < SCAN_B) g_partoff[lane] = incl - v;
    if (lane == 31) g_offs[NN] = incl;
}

// Stage 3: per-block exclusive scan with base -> g_offs / g_cursor.
__global__ __launch_bounds__(1024) void rgcn_scan_final() {
    const int tid = threadIdx.x, lane = tid & 31, w = tid >> 5;
    __shared__ int wsum[32];
    int i0 = blockIdx.x * 4096 + tid * 4;
    int v[4], s = 0;
#pragma unroll
    for (int q = 0; q < 4; q++) {
        int i = i0 + q;
        v[q] = (i < NN) ? g_counts[i] : 0;
        s += v[q];
    }
    int incl = s;
#pragma unroll
    for (int off = 1; off < 32; off <<= 1) {
        int t = __shfl_up_sync(~0u, incl, off);
        if (lane >= off) incl += t;
    }
    if (lane == 31) wsum[w] = incl;
    __syncthreads();
    if (w == 0) {
        int x = wsum[lane];
#pragma unroll
        for (int off = 1; off < 32; off <<= 1) {
            int t = __shfl_up_sync(~0u, x, off);
            if (lane >= off) x += t;
        }
        wsum[lane] = x;
    }
    __syncthreads();
    int run = g_partoff[blockIdx.x] + (w ? wsum[w - 1] : 0) + incl - s;
#pragma unroll
    for (int q = 0; q < 4; q++) {
        int i = i0 + q;
        if (i < NN) { g_offs[i] = run; g_cursor[i] = run; }
        run += v[q];
    }
}

__global__ __launch_bounds__(256) void rgcn_scatter(const int* __restrict__ esrc,
                                                    const int* __restrict__ etype,
                                                    const float* __restrict__ enorm,
                                                    const int* __restrict__ edst) {
    int e = blockIdx.x * 256 + threadIdx.x;
    if (e >= NE) return;
    int d = __ldg(edst + e);
    int pos = atomicAdd(&g_cursor[d], 1);
    g_epack[pos] = make_int2(__ldg(esrc + e) * NR + __ldg(etype + e),
                             __float_as_int(__ldg(enorm + e)));
}

// ---------------------------------------------------------------------------
// Kernel 1: ht[m0+row][r][:] = h_tile @ W_r  (fp16 single pass, mma.sync).
// 2 CTAs/SM; 4(M)x2(N) warps; warp tile 32x64.
// ---------------------------------------------------------------------------
__global__ __launch_bounds__(256, 2) void rgcn_mma_gemm() {
    extern __shared__ char smem[];
    const uint32_t raw  = smem_u32(smem);
    const uint32_t base = (raw + 1023u) & ~1023u;

    const uint32_t A_T = base;
    const uint32_t B_T = base + 32768;

    const int tid  = threadIdx.x;
    const int wid  = tid >> 5;
    const int lane = tid & 31;
    const int r    = blockIdx.x;
    const int m0   = blockIdx.y * 128;

    const int mwarp = wid & 3;
    const int nwarp = wid >> 2;

    const int row_a = (lane & 7) + ((lane >> 3) & 1) * 8;
    const int ka    = ((lane >> 4) & 1) * 8;
    const int row_b = (lane & 7) + ((lane >> 4) & 1) * 8;
    const int kb    = ((lane >> 3) & 1) * 8;

    float acc[2][8][4];
#pragma unroll
    for (int mi = 0; mi < 2; mi++)
#pragma unroll
        for (int nj = 0; nj < 8; nj++)
#pragma unroll
            for (int q = 0; q < 4; q++) acc[mi][nj][q] = 0.0f;

    const __half* wf = g_wf + (size_t)r * FD * FD;

    // tile = 2048 x 16B chunks; 8 chunks/thread: row = idx>>4, k = (idx&15)*8
#pragma unroll
    for (int q = 0; q < 8; q++) {
        int idx = tid * 8 + q;
        int row = idx >> 4;
        int k   = (idx & 15) * 8;
        int n   = m0 + row;
        cpasync16(A_T + tile_off(row, k), g_hf + (size_t)n * FD + k,
                  (n < NN) ? 16 : 0);
        cpasync16(B_T + tile_off(row, k), wf + row * FD + k, 16);
    }
    CP_COMMIT();
    CP_WAIT0();
    __syncthreads();

#pragma unroll
    for (int k0 = 0; k0 < 128; k0 += 16) {
        uint32_t af[2][4];
#pragma unroll
        for (int mi = 0; mi < 2; mi++)
            ldm_x4(af[mi], A_T + tile_off(mwarp * 32 + mi * 16 + row_a, k0 + ka));
        uint32_t bh[4][4];
#pragma unroll
        for (int q = 0; q < 4; q++)
            ldm_x4(bh[q], B_T + tile_off(nwarp * 64 + q * 16 + row_b, k0 + kb));
#pragma unroll
        for (int mi = 0; mi < 2; mi++)
#pragma unroll
            for (int nj = 0; nj < 8; nj++)
                mma_16816(acc[mi][nj], af[mi],
                          bh[nj >> 1][(nj & 1) * 2], bh[nj >> 1][(nj & 1) * 2 + 1]);
    }

    // --- Epilogue: fp16 stores ---
    const int crow = lane >> 2;
    const int ccol = (lane & 3) * 2;
#pragma unroll
    for (int mi = 0; mi < 2; mi++) {
        int row0 = mwarp * 32 + mi * 16 + crow;
        int n0 = m0 + row0;
        int n1 = n0 + 8;
        __half* d0 = g_ht + ((size_t)n0 * NR + r) * FD + nwarp * 64 + ccol;
        __half* d1 = g_ht + ((size_t)n1 * NR + r) * FD + nwarp * 64 + ccol;
#pragma unroll
        for (int nj = 0; nj < 8; nj++) {
            if (n0 < NN) *(__half2*)(d0 + nj * 8) = __floats2half2_rn(acc[mi][nj][0], acc[mi][nj][1]);
            if (n1 < NN) *(__half2*)(d1 + nj * 8) = __floats2half2_rn(acc[mi][nj][2], acc[mi][nj][3]);
        }
    }
}

// ---------------------------------------------------------------------------
// Kernel 2: per-node aggregation over dst-CSR + bias + relu, plain stores.
// One warp per node; lane l owns floats [4l, 4l+4).
// ---------------------------------------------------------------------------
__global__ __launch_bounds__(256) void rgcn_agg(const float* __restrict__ bias,
                                                float* __restrict__ out) {
    const int n = blockIdx.x * 8 + (threadIdx.x >> 5);
    if (n >= NN) return;
    const int lane = threadIdx.x & 31;

    const int beg = __ldg(&g_offs[n]);
    const int end = __ldg(&g_offs[n + 1]);

    float a0 = 0.f, a1 = 0.f, a2 = 0.f, a3 = 0.f;

    int i = beg;
    if (i < end) {
        int2 p = __ldg(&g_epack[i]);
        while (true) {
            int2 cur = p;
            if (i + 1 < end) p = __ldg(&g_epack[i + 1]);
            float nv = __int_as_float(cur.y);
            uint2 rawv = __ldg((const uint2*)(g_ht + (size_t)cur.x * FD) + lane);
            float2 f0 = __half22float2(*(__half2*)&rawv.x);
            float2 f1 = __half22float2(*(__half2*)&rawv.y);
            a0 = fmaf(nv, f0.x, a0);
            a1 = fmaf(nv, f0.y, a1);
            a2 = fmaf(nv, f1.x, a2);
            a3 = fmaf(nv, f1.y, a3);
            if (++i >= end) break;
        }
    }

    float4 b = __ldg((const float4*)bias + lane);
    float4 o;
    o.x = fmaxf(a0 + b.x, 0.0f);
    o.y = fmaxf(a1 + b.y, 0.0f);
    o.z = fmaxf(a2 + b.z, 0.0f);
    o.w = fmaxf(a3 + b.w, 0.0f);
    *(float4*)(out + (size_t)n * FD + lane * 4) = o;
}

extern "C" void kernel_launch(void* const* d_in, const int* in_sizes, int n_in,
                              void* d_out, int out_size) {
    const float* h     = (const float*)d_in[0];
    const float* enorm = (const float*)d_in[1];
    const int*   etype = (const int*)d_in[2];
    const int*   esrc  = (const int*)d_in[3];
    const int*   edst  = (const int*)d_in[4];
    const float* w     = (const float*)d_in[5];
    const float* bias  = (const float*)d_in[6];
    float* out = (float*)d_out;

    cudaFuncSetAttribute(rgcn_mma_gemm, cudaFuncAttributeMaxDynamicSharedMemorySize,
                         SMEM_BYTES);

    // zero CSR counters
    void* cptr = nullptr;
    cudaGetSymbolAddress(&cptr, g_counts);
    cudaMemsetAsync(cptr, 0, NN * sizeof(int), 0);

    rgcn_wprep<<<(NR * FD * FD + 255) / 256, 256>>>(w);
    rgcn_hprep<<<(NN * FD / 2 + 255) / 256, 256>>>(h);

    rgcn_hist<<<(NE + 255) / 256, 256>>>(edst);
    rgcn_scan_part<<<SCAN_B, 1024>>>();
    rgcn_scan_mid<<<1, 32>>>();
    rgcn_scan_final<<<SCAN_B, 1024>>>();
    rgcn_scatter<<<(NE + 255) / 256, 256>>>(esrc, etype, enorm, edst);

    dim3 gg(NR, M_TILES);
    rgcn_mma_gemm<<<gg, 256, SMEM_BYTES>>>();

    rgcn_agg<<<(NN + 7) / 8, 256>>>(bias, out);
}

// round 11
// speedup vs baseline: 3.0594x; 1.0111x over previous
#include <cuda_runtime.h>
#include <cuda_fp16.h>
#include <cstdint>

#define NN 50000
#define NE 800000
#define NR 8
#define FD 128

#define M_TILES ((NN + 127) / 128)        // 391
#define SMEM_BYTES (1024 + 3 * 32768)     // align slack + A + B0 + B1 = 99328
#define SCAN_B ((NN + 4095) / 4096)       // 13

// Scratch: ht[n][r][o] fp16, 102.4 MB (fits L2).
__device__ __half g_ht[(size_t)NN * NR * FD];
// W fp16 transposed: [r][o][i]
__device__ __half g_wf[NR * FD * FD];
// h fp16: [n][i]
__device__ __half g_hf[(size_t)NN * FD];
// dst-CSR scratch
__device__ int  g_counts[NN];
__device__ int  g_offs[NN + 1];
__device__ int  g_cursor[NN];
__device__ int  g_part[32];
__device__ int  g_partoff[32];
__device__ int2 g_epack[NE];              // {src*NR+type, norm bits}

// ---------------------------------------------------------------------------
__device__ __forceinline__ uint32_t smem_u32(const void* p) {
    uint32_t a;
    asm("{ .reg .u64 t; cvta.to.shared.u64 t, %1; cvt.u32.u64 %0, t; }" : "=r"(a) : "l"(p));
    return a;
}

// Blocked SW128 K-major layout for a [128 rows x 128 fp16] tile.
__device__ __forceinline__ uint32_t tile_off(int row, int k) {
    uint32_t b = ((uint32_t)(row >> 3) + (uint32_t)(k >> 6) * 16u) * 1024u
               + (uint32_t)(row & 7) * 128u + (uint32_t)(k & 63) * 2u;
    return b ^ ((b >> 3) & 0x70u);
}

__device__ __forceinline__ void ldm_x4(uint32_t* r, uint32_t addr) {
    asm volatile("ldmatrix.sync.aligned.m8n8.x4.shared.b16 {%0,%1,%2,%3}, [%4];"
                 : "=r"(r[0]), "=r"(r[1]), "=r"(r[2]), "=r"(r[3]) : "r"(addr));
}

__device__ __forceinline__ void mma_16816(float* c, const uint32_t* a,
                                          uint32_t b0, uint32_t b1) {
    asm volatile(
        "mma.sync.aligned.m16n8k16.row.col.f32.f16.f16.f32 "
        "{%0,%1,%2,%3}, {%4,%5,%6,%7}, {%8,%9}, {%0,%1,%2,%3};"
        : "+f"(c[0]), "+f"(c[1]), "+f"(c[2]), "+f"(c[3])
        : "r"(a[0]), "r"(a[1]), "r"(a[2]), "r"(a[3]), "r"(b0), "r"(b1));
}

__device__ __forceinline__ void cpasync16(uint32_t dst, const void* src, int sz) {
    asm volatile("cp.async.cg.shared.global [%0], [%1], 16, %2;"
                 :: "r"(dst), "l"(src), "r"(sz) : "memory");
}
#define CP_COMMIT() asm volatile("cp.async.commit_group;" ::: "memory")
#define CP_WAIT0()  asm volatile("cp.async.wait_group 0;" ::: "memory")
#define CP_WAIT1()  asm volatile("cp.async.wait_group 1;" ::: "memory")

// ---------------------------------------------------------------------------
// Kernel 0a: W fp32 [r][i][o] -> fp16 transposed [r][o][i].
// ---------------------------------------------------------------------------
__global__ __launch_bounds__(256) void rgcn_wprep(const float* __restrict__ w) {
    int idx = blockIdx.x * 256 + threadIdx.x;
    if (idx >= NR * FD * FD) return;
    int r = idx >> 14, rem = idx & 16383;
    int o = rem >> 7, i = rem & 127;
    g_wf[idx] = __float2half_rn(w[((size_t)r * FD + i) * FD + o]);
}

// ---------------------------------------------------------------------------
// Kernel 0b: h fp32 -> fp16.
// ---------------------------------------------------------------------------
__global__ __launch_bounds__(256) void rgcn_hprep(const float* __restrict__ h) {
    int idx = blockIdx.x * 256 + threadIdx.x;        // float2 granule
    const int total = NN * FD / 2;
    if (idx >= total) return;
    float2 v = ((const float2*)h)[idx];
    ((__half2*)g_hf)[idx] = __floats2half2_rn(v.x, v.y);
}

// ---------------------------------------------------------------------------
// CSR build: histogram -> 3-stage parallel scan -> scatter.
// ---------------------------------------------------------------------------
__global__ __launch_bounds__(256) void rgcn_hist(const int* __restrict__ edst) {
    int e = blockIdx.x * 256 + threadIdx.x;
    if (e < NE) atomicAdd(&g_counts[__ldg(edst + e)], 1);
}

__global__ __launch_bounds__(1024) void rgcn_scan_part() {
    const int tid = threadIdx.x, lane = tid & 31, w = tid >> 5;
    __shared__ int ws[32];
    int i0 = blockIdx.x * 4096 + tid * 4;
    int s = 0;
#pragma unroll
    for (int q = 0; q < 4; q++) {
        int i = i0 + q;
        if (i < NN) s += g_counts[i];
    }
#pragma unroll
    for (int off = 16; off; off >>= 1) s += __shfl_down_sync(~0u, s, off);
    if (lane == 0) ws[w] = s;
    __syncthreads();
    if (w == 0) {
        int x = ws[lane];
#pragma unroll
        for (int off = 16; off; off >>= 1) x += __shfl_down_sync(~0u, x, off);
        if (lane == 0) g_part[blockIdx.x] = x;
    }
}

__global__ void rgcn_scan_mid() {
    int lane = threadIdx.x;
    int v = (lane < SCAN_B) ? g_part[lane] : 0;
    int incl = v;
#pragma unroll
    for (int off = 1; off < 32; off <<= 1) {
        int t = __shfl_up_sync(~0u, incl, off);
        if (lane >= off) incl += t;
    }
    if (lane < SCAN_B) g_partoff[lane] = incl - v;
    if (lane == 31) g_offs[NN] = incl;
}

__global__ __launch_bounds__(1024) void rgcn_scan_final() {
    const int tid = threadIdx.x, lane = tid & 31, w = tid >> 5;
    __shared__ int wsum[32];
    int i0 = blockIdx.x * 4096 + tid * 4;
    int v[4], s = 0;
#pragma unroll
    for (int q = 0; q < 4; q++) {
        int i = i0 + q;
        v[q] = (i < NN) ? g_counts[i] : 0;
        s += v[q];
    }
    int incl = s;
#pragma unroll
    for (int off = 1; off < 32; off <<= 1) {
        int t = __shfl_up_sync(~0u, incl, off);
        if (lane >= off) incl += t;
    }
    if (lane == 31) wsum[w] = incl;
    __syncthreads();
    if (w == 0) {
        int x = wsum[lane];
#pragma unroll
        for (int off = 1; off < 32; off <<= 1) {
            int t = __shfl_up_sync(~0u, x, off);
            if (lane >= off) x += t;
        }
        wsum[lane] = x;
    }
    __syncthreads();
    int run = g_partoff[blockIdx.x] + (w ? wsum[w - 1] : 0) + incl - s;
#pragma unroll
    for (int q = 0; q < 4; q++) {
        int i = i0 + q;
        if (i < NN) { g_offs[i] = run; g_cursor[i] = run; }
        run += v[q];
    }
}

__global__ __launch_bounds__(256) void rgcn_scatter(const int* __restrict__ esrc,
                                                    const int* __restrict__ etype,
                                                    const float* __restrict__ enorm,
                                                    const int* __restrict__ edst) {
    int e = blockIdx.x * 256 + threadIdx.x;
    if (e >= NE) return;
    int d = __ldg(edst + e);
    int pos = atomicAdd(&g_cursor[d], 1);
    g_epack[pos] = make_int2(__ldg(esrc + e) * NR + __ldg(etype + e),
                             __float_as_int(__ldg(enorm + e)));
}

// ---------------------------------------------------------------------------
// Kernel 1: for each node tile, loop over all 8 relations with A resident
// and B double-buffered via cp.async. fp16 single-pass mma.sync; 2 CTAs/SM.
// ---------------------------------------------------------------------------
__global__ __launch_bounds__(256, 2) void rgcn_mma_gemm() {
    extern __shared__ char smem[];
    const uint32_t raw  = smem_u32(smem);
    const uint32_t base = (raw + 1023u) & ~1023u;

    const uint32_t A_T = base;
    const uint32_t B_B[2] = {base + 32768, base + 65536};

    const int tid  = threadIdx.x;
    const int wid  = tid >> 5;
    const int lane = tid & 31;
    const int m0   = blockIdx.x * 128;

    const int mwarp = wid & 3;
    const int nwarp = wid >> 2;

    const int row_a = (lane & 7) + ((lane >> 3) & 1) * 8;
    const int ka    = ((lane >> 4) & 1) * 8;
    const int row_b = (lane & 7) + ((lane >> 4) & 1) * 8;
    const int kb    = ((lane >> 3) & 1) * 8;

    // Per-thread load geometry: tile = 2048 x 16B chunks; 8 chunks/thread.
    int lrow[8], lk[8];
#pragma unroll
    for (int q = 0; q < 8; q++) {
        int idx = tid * 8 + q;
        lrow[q] = idx >> 4;
        lk[q]   = (idx & 15) * 8;
    }

    // Prologue: group0 = A + B_0
#pragma unroll
    for (int q = 0; q < 8; q++) {
        int n = m0 + lrow[q];
        cpasync16(A_T + tile_off(lrow[q], lk[q]), g_hf + (size_t)n * FD + lk[q],
                  (n < NN) ? 16 : 0);
        cpasync16(B_B[0] + tile_off(lrow[q], lk[q]), g_wf + lrow[q] * FD + lk[q], 16);
    }
    CP_COMMIT();

    const int crow = lane >> 2;
    const int ccol = (lane & 3) * 2;

    for (int r = 0; r < NR; r++) {
        const uint32_t CUR = B_B[r & 1];
        // Prefetch B_{r+1} into the other buffer (its readers finished at the
        // previous iteration's trailing __syncthreads).
        if (r + 1 < NR) {
            const __half* wn = g_wf + (size_t)(r + 1) * FD * FD;
            const uint32_t NXT = B_B[(r + 1) & 1];
#pragma unroll
            for (int q = 0; q < 8; q++)
                cpasync16(NXT + tile_off(lrow[q], lk[q]), wn + lrow[q] * FD + lk[q], 16);
            CP_COMMIT();
            CP_WAIT1();          // B_r (and A) complete; B_{r+1} may be pending
        } else {
            CP_WAIT0();
        }
        __syncthreads();

        float acc[2][8][4];
#pragma unroll
        for (int mi = 0; mi < 2; mi++)
#pragma unroll
            for (int nj = 0; nj < 8; nj++)
#pragma unroll
                for (int q = 0; q < 4; q++) acc[mi][nj][q] = 0.0f;

#pragma unroll
        for (int k0 = 0; k0 < 128; k0 += 16) {
            uint32_t af[2][4];
#pragma unroll
            for (int mi = 0; mi < 2; mi++)
                ldm_x4(af[mi], A_T + tile_off(mwarp * 32 + mi * 16 + row_a, k0 + ka));
            uint32_t bh[4][4];
#pragma unroll
            for (int q = 0; q < 4; q++)
                ldm_x4(bh[q], CUR + tile_off(nwarp * 64 + q * 16 + row_b, k0 + kb));
#pragma unroll
            for (int mi = 0; mi < 2; mi++)
#pragma unroll
                for (int nj = 0; nj < 8; nj++)
                    mma_16816(acc[mi][nj], af[mi],
                              bh[nj >> 1][(nj & 1) * 2], bh[nj >> 1][(nj & 1) * 2 + 1]);
        }

        // Epilogue for relation r (register-sourced; no smem hazard)
#pragma unroll
        for (int mi = 0; mi < 2; mi++) {
            int row0 = mwarp * 32 + mi * 16 + crow;
            int n0 = m0 + row0;
            int n1 = n0 + 8;
            __half* d0 = g_ht + ((size_t)n0 * NR + r) * FD + nwarp * 64 + ccol;
            __half* d1 = g_ht + ((size_t)n1 * NR + r) * FD + nwarp * 64 + ccol;
#pragma unroll
            for (int nj = 0; nj < 8; nj++) {
                if (n0 < NN) *(__half2*)(d0 + nj * 8) = __floats2half2_rn(acc[mi][nj][0], acc[mi][nj][1]);
                if (n1 < NN) *(__half2*)(d1 + nj * 8) = __floats2half2_rn(acc[mi][nj][2], acc[mi][nj][3]);
            }
        }
        __syncthreads();   // all reads of CUR done before next iter's prefetch overwrites it
    }
}

// ---------------------------------------------------------------------------
// Kernel 2: per-node aggregation over dst-CSR + bias + relu (2-edge ILP).
// One warp per node; lane l owns floats [4l, 4l+4).
// ---------------------------------------------------------------------------
__global__ __launch_bounds__(256) void rgcn_agg(const float* __restrict__ bias,
                                                float* __restrict__ out) {
    const int n = blockIdx.x * 8 + (threadIdx.x >> 5);
    if (n >= NN) return;
    const int lane = threadIdx.x & 31;

    const int beg = __ldg(&g_offs[n]);
    const int end = __ldg(&g_offs[n + 1]);

    float a0 = 0.f, a1 = 0.f, a2 = 0.f, a3 = 0.f;

    int i = beg;
    for (; i + 1 < end; i += 2) {
        int2 p0 = __ldg(&g_epack[i]);
        int2 p1 = __ldg(&g_epack[i + 1]);
        uint2 r0 = __ldg((const uint2*)(g_ht + (size_t)p0.x * FD) + lane);
        uint2 r1 = __ldg((const uint2*)(g_ht + (size_t)p1.x * FD) + lane);
        float nv0 = __int_as_float(p0.y);
        float nv1 = __int_as_float(p1.y);
        float2 x0 = __half22float2(*(__half2*)&r0.x);
        float2 x1 = __half22float2(*(__half2*)&r0.y);
        float2 y0 = __half22float2(*(__half2*)&r1.x);
        float2 y1 = __half22float2(*(__half2*)&r1.y);
        a0 = fmaf(nv0, x0.x, a0); a1 = fmaf(nv0, x0.y, a1);
        a2 = fmaf(nv0, x1.x, a2); a3 = fmaf(nv0, x1.y, a3);
        a0 = fmaf(nv1, y0.x, a0); a1 = fmaf(nv1, y0.y, a1);
        a2 = fmaf(nv1, y1.x, a2); a3 = fmaf(nv1, y1.y, a3);
    }
    if (i < end) {
        int2 p0 = __ldg(&g_epack[i]);
        uint2 r0 = __ldg((const uint2*)(g_ht + (size_t)p0.x * FD) + lane);
        float nv0 = __int_as_float(p0.y);
        float2 x0 = __half22float2(*(__half2*)&r0.x);
        float2 x1 = __half22float2(*(__half2*)&r0.y);
        a0 = fmaf(nv0, x0.x, a0); a1 = fmaf(nv0, x0.y, a1);
        a2 = fmaf(nv0, x1.x, a2); a3 = fmaf(nv0, x1.y, a3);
    }

    float4 b = __ldg((const float4*)bias + lane);
    float4 o;
    o.x = fmaxf(a0 + b.x, 0.0f);
    o.y = fmaxf(a1 + b.y, 0.0f);
    o.z = fmaxf(a2 + b.z, 0.0f);
    o.w = fmaxf(a3 + b.w, 0.0f);
    *(float4*)(out + (size_t)n * FD + lane * 4) = o;
}

extern "C" void kernel_launch(void* const* d_in, const int* in_sizes, int n_in,
                              void* d_out, int out_size) {
    const float* h     = (const float*)d_in[0];
    const float* enorm = (const float*)d_in[1];
    const int*   etype = (const int*)d_in[2];
    const int*   esrc  = (const int*)d_in[3];
    const int*   edst  = (const int*)d_in[4];
    const float* w     = (const float*)d_in[5];
    const float* bias  = (const float*)d_in[6];
    float* out = (float*)d_out;

    cudaFuncSetAttribute(rgcn_mma_gemm, cudaFuncAttributeMaxDynamicSharedMemorySize,
                         SMEM_BYTES);

    // zero CSR counters
    void* cptr = nullptr;
    cudaGetSymbolAddress(&cptr, g_counts);
    cudaMemsetAsync(cptr, 0, NN * sizeof(int), 0);

    rgcn_wprep<<<(NR * FD * FD + 255) / 256, 256>>>(w);
    rgcn_hprep<<<(NN * FD / 2 + 255) / 256, 256>>>(h);

    rgcn_hist<<<(NE + 255) / 256, 256>>>(edst);
    rgcn_scan_part<<<SCAN_B, 1024>>>();
    rgcn_scan_mid<<<1, 32>>>();
    rgcn_scan_final<<<SCAN_B, 1024>>>();
    rgcn_scatter<<<(NE + 255) / 256, 256>>>(esrc, etype, enorm, edst);

    rgcn_mma_gemm<<<M_TILES, 256, SMEM_BYTES>>>();

    rgcn_agg<<<(NN + 7) / 8, 256>>>(bias, out);
}